// round 5
// baseline (speedup 1.0000x reference)
#include <cuda_runtime.h>
#include <cuda_bf16.h>

// 16k -> 24k Kaldi polyphase resampler.
//   in_unit = 2, out_unit = 3, W = 13 taps, first_indices = {-6,-5,-4}
//   out[c, 3u+p] = sum_{j=0}^{12} x[c, 2u + (p-6) + j] * w[p][j]   (zero-padded)
//
// Block tiling: RS_UPB units (3*RS_UPB outputs) per CTA, one channel per
// blockIdx.y. Input segment staged in SMEM (zero-padded at both ends); each
// thread register-blocks 2 units x 3 phases = 6 outputs from 17 staged floats
// (4x LDS.128 + 1 scalar LDS), weights held in registers.
//
// Staging fast path: interior CTAs (segment fully inside [0,L)) load the
// segment with float2 LDG.64 (pointer is 8B-aligned since s0 is even) —
// halves LSU issue count and removes per-element predication vs scalar loads.

#define RS_THREADS 256
#define RS_GROUPS  4
#define RS_PAIRS   (RS_THREADS * RS_GROUPS)   // 1024 unit-pairs per block
#define RS_UPB     (RS_PAIRS * 2)             // 2048 units per block
#define RS_SEG     (2 * RS_UPB + 20)          // 4116 floats staged (16.5 KB)
#define RS_SEG2    (RS_SEG / 2)               // 2058 float2

__global__ __launch_bounds__(RS_THREADS)
void resample_16k_24k_kernel(const float* __restrict__ x,
                             const float* __restrict__ w,
                             float* __restrict__ y,
                             int L, int tot)
{
    __shared__ __align__(16) float s[RS_SEG];
    __shared__ float sw[40];

    const int c  = blockIdx.y;
    const int u0 = blockIdx.x * RS_UPB;                 // first unit of block
    const float* xc = x + (size_t)c * (size_t)L;
    float*       yc = y + (size_t)c * (size_t)tot;

    // Stage the 39 weights through SMEM (broadcast LDS later, keeps LSU free).
    if (threadIdx.x < 39) sw[threadIdx.x] = w[threadIdx.x];

    // Stage input segment: s[i] = x[2*u0 - 6 + i], zero outside [0, L).
    const int s0 = 2 * u0 - 6;                          // always even
    if (s0 >= 0 && s0 + RS_SEG <= L) {
        // Fast path: fully interior — vectorized, unpredicated LDG.64.
        const float2* xg = (const float2*)(xc + s0);    // 8B-aligned
        float2* sg = (float2*)s;
        #pragma unroll
        for (int k = 0; k < RS_SEG2 / RS_THREADS; k++)
            sg[k * RS_THREADS + threadIdx.x] = __ldg(xg + k * RS_THREADS + threadIdx.x);
        // Remainder: RS_SEG2 = 2058 = 8*256 + 10
        if (threadIdx.x < RS_SEG2 - (RS_SEG2 / RS_THREADS) * RS_THREADS)
            sg[(RS_SEG2 / RS_THREADS) * RS_THREADS + threadIdx.x] =
                __ldg(xg + (RS_SEG2 / RS_THREADS) * RS_THREADS + threadIdx.x);
    } else {
        // Edge blocks (first/last per channel): scalar bounds-checked loads.
        for (int i = threadIdx.x; i < RS_SEG; i += RS_THREADS) {
            const int g = s0 + i;
            s[i] = (g >= 0 && g < L) ? __ldg(xc + g) : 0.0f;
        }
    }
    __syncthreads();

    // Weights to registers (uniform per thread; 39 broadcast LDS).
    float wr[3][13];
    #pragma unroll
    for (int p = 0; p < 3; p++)
        #pragma unroll
        for (int j = 0; j < 13; j++)
            wr[p][j] = sw[p * 13 + j];

    const float4* s4 = (const float4*)s;

    #pragma unroll
    for (int gix = 0; gix < RS_GROUPS; gix++) {
        const int q = gix * RS_THREADS + threadIdx.x;   // unit-pair index
        // Load s[4q .. 4q+16]: units (2q, 2q+1), all phases, all taps.
        const float4 v0 = s4[q];
        const float4 v1 = s4[q + 1];
        const float4 v2 = s4[q + 2];
        const float4 v3 = s4[q + 3];
        const float d16 = s[4 * q + 16];
        const float d[17] = {v0.x, v0.y, v0.z, v0.w,
                             v1.x, v1.y, v1.z, v1.w,
                             v2.x, v2.y, v2.z, v2.w,
                             v3.x, v3.y, v3.z, v3.w, d16};

        float a[6];
        #pragma unroll
        for (int p = 0; p < 3; p++) {
            float a0 = 0.0f, a1 = 0.0f;
            #pragma unroll
            for (int j = 0; j < 13; j++) {
                a0 = fmaf(d[p + j],     wr[p][j], a0);  // unit 2q
                a1 = fmaf(d[p + j + 2], wr[p][j], a1);  // unit 2q+1
            }
            a[p]     = a0;
            a[p + 3] = a1;
        }

        // Outputs n0..n0+5 are contiguous; n0 is even -> float2 stores OK.
        const int n0 = 3 * u0 + 6 * q;
        if (n0 + 6 <= tot) {
            float2* yp = (float2*)(yc + n0);
            yp[0] = make_float2(a[0], a[1]);
            yp[1] = make_float2(a[2], a[3]);
            yp[2] = make_float2(a[4], a[5]);
        } else {
            #pragma unroll
            for (int k = 0; k < 6; k++)
                if (n0 + k < tot) yc[n0 + k] = a[k];
        }
    }
}

extern "C" void kernel_launch(void* const* d_in, const int* in_sizes, int n_in,
                              void* d_out, int out_size)
{
    // Inputs: waveform [8, L] float32, weights [3, 13] float32 (order per
    // metadata; be defensive about ordering via element counts).
    int wav_i = 0, wts_i = 1;
    if (n_in >= 2 && in_sizes[0] < in_sizes[1]) { wav_i = 1; wts_i = 0; }

    const float* wav = (const float*)d_in[wav_i];
    const float* wts = (const float*)d_in[wts_i];
    float* out = (float*)d_out;

    const int C   = 8;
    const int L   = in_sizes[wav_i] / C;
    const int tot = out_size / C;                 // = 3L/2 = 6,000,000
    const int tot_units = (tot + 2) / 3;          // ceil(tot / 3)

    dim3 grid((tot_units + RS_UPB - 1) / RS_UPB, C);
    resample_16k_24k_kernel<<<grid, RS_THREADS>>>(wav, wts, out, L, tot);
}